// round 13
// baseline (speedup 1.0000x reference)
#include <cuda_runtime.h>
#include <cstdint>

// ---------------------------------------------------------------------------
// HungarianPredictor: B=2048, N=24, D=256
//   cost[b,i,j] = 1 - <normalize(prev[b,i]), normalize(slots[b,j])>
//   col = hungarian(cost)  (Jonker-Volgenant / e-maxx formulation)
//   out[b,i,:] = slots[b, col[b,i], :]
// ---------------------------------------------------------------------------

#define NSLOT   24
#define DDIM    256
#define ROWPAD  260                    // 1040 B row stride: 16B aligned, 8-lane-phase conflict-free
#define NN      (NSLOT * NSLOT)        // 576
#define MAXB    2048
#define HINF    1e9f

static const int SMEM_BYTES = 48 * ROWPAD * 4;   // 49,920 B (prev rows 0..23, cur rows 24..47)

__device__ float g_cost[MAXB * NN];
__device__ int   g_col [MAXB * NSLOT];

__device__ __forceinline__ unsigned long long fma2(unsigned long long a,
                                                   unsigned long long b,
                                                   unsigned long long c) {
    unsigned long long d;
    asm("fma.rn.f32x2 %0, %1, %2, %3;" : "=l"(d) : "l"(a), "l"(b), "l"(c));
    return d;
}

__device__ __forceinline__ float hsum2(unsigned long long v) {
    float lo = __uint_as_float((unsigned)(v & 0xffffffffu));
    float hi = __uint_as_float((unsigned)(v >> 32));
    return lo + hi;
}

// ---------------------------------------------------------------------------
// Kernel 1: per-batch cost matrix.  One block per batch, 256 threads.
//   load+norm fused: warp w stages 6 rows (w<4: prev, w>=4: cur) and computes
//   their inverse norms directly from the load registers.
//   dot split-K over ALL 8 warps: warp (w&3) -> prev rows 6(w&3)..6(w&3)+5,
//   (w>>2) -> K half; lane j -> cur col j.  Upper-half warps deposit partials
//   in smem; lower-half warps combine + fold norms:  1 - dot*inv_i*inv_j.
// ---------------------------------------------------------------------------
__global__ __launch_bounds__(256)
void cost_kernel(const float* __restrict__ slots, const float* __restrict__ prev) {
    extern __shared__ float s[];
    __shared__ float s_inv[48];
    __shared__ float s_part[4][6][NSLOT];
    const int b    = blockIdx.x;
    const int tid  = threadIdx.x;
    const int w    = tid >> 5;
    const int lane = tid & 31;

    // ---- load 6 rows per warp + fused sum-of-squares ----
    const int srow = (w < 4) ? 6 * w : NSLOT + 6 * (w - 4);
    const float* base = (w < 4) ? (prev  + (size_t)b * (NSLOT * DDIM) + (6 * w) * DDIM)
                                : (slots + (size_t)b * (NSLOT * DDIM) + (6 * (w - 4)) * DDIM);
    float4 v0[6], v1[6];
    #pragma unroll
    for (int rr = 0; rr < 6; ++rr) {               // 12 LDGs in flight
        const float4* rp = (const float4*)(base + rr * DDIM);
        v0[rr] = rp[lane];
        v1[rr] = rp[lane + 32];
    }
    #pragma unroll
    for (int rr = 0; rr < 6; ++rr) {
        *(float4*)&s[(srow + rr) * ROWPAD + lane * 4]        = v0[rr];
        *(float4*)&s[(srow + rr) * ROWPAD + (lane + 32) * 4] = v1[rr];
        float ss = v0[rr].x * v0[rr].x;
        ss = fmaf(v0[rr].y, v0[rr].y, ss);
        ss = fmaf(v0[rr].z, v0[rr].z, ss);
        ss = fmaf(v0[rr].w, v0[rr].w, ss);
        ss = fmaf(v1[rr].x, v1[rr].x, ss);
        ss = fmaf(v1[rr].y, v1[rr].y, ss);
        ss = fmaf(v1[rr].z, v1[rr].z, ss);
        ss = fmaf(v1[rr].w, v1[rr].w, ss);
        #pragma unroll
        for (int o = 16; o; o >>= 1) ss += __shfl_xor_sync(0xffffffffu, ss, o);
        if (lane == 0) s_inv[srow + rr] = 1.f / fmaxf(sqrtf(ss), 1e-12f);
    }
    __syncthreads();

    // ---- split-K dot: warp (w&3) -> 6 prev rows, (w>>2) -> K half ----
    const int wa    = w & 3;
    const int khalf = w >> 2;
    const int r0    = wa * 6;
    const int kofs  = khalf * 128;                 // 32 float4 per half

    unsigned long long acc[6];
    #pragma unroll
    for (int rr = 0; rr < 6; ++rr) acc[rr] = 0ull;

    if (lane < NSLOT) {
        const float* cj = &s[(NSLOT + lane) * ROWPAD + kofs];
        #pragma unroll 4
        for (int k4 = 0; k4 < 32; ++k4) {
            ulonglong2 c = *(const ulonglong2*)&cj[k4 * 4];      // conflict-free per 8-lane phase
            #pragma unroll
            for (int rr = 0; rr < 6; ++rr) {
                ulonglong2 a = *(const ulonglong2*)&s[(r0 + rr) * ROWPAD + kofs + k4 * 4];  // broadcast
                acc[rr] = fma2(a.x, c.x, acc[rr]);
                acc[rr] = fma2(a.y, c.y, acc[rr]);
            }
        }
        if (khalf == 1) {
            #pragma unroll
            for (int rr = 0; rr < 6; ++rr) s_part[wa][rr][lane] = hsum2(acc[rr]);
        }
    }
    __syncthreads();

    if (khalf == 0 && lane < NSLOT) {
        const float invj = s_inv[NSLOT + lane];
        float* cg = g_cost + (size_t)b * NN;
        #pragma unroll
        for (int rr = 0; rr < 6; ++rr) {
            float dot = hsum2(acc[rr]) + s_part[wa][rr][lane];
            cg[(r0 + rr) * NSLOT + lane] = 1.f - dot * s_inv[r0 + rr] * invj;
        }
    }
}

// ---------------------------------------------------------------------------
// Kernel 2: Hungarian (JV shortest augmenting path), one warp per batch.
// Lane j owns column j (j=24 is the virtual start column).  All duals in
// registers: v[j], minv[j], way[j], p[j], up[j]=u[p[j]].  The (i0,u0) for the
// next iteration are shuffled at the BOTTOM of the loop (merged with the
// break check), so the cost-row LDS issues at iteration start with no shfl
// in front of it.  Argmin = order-preserving uint key + redux.min +
// ballot/ffs (first-index tie-break, identical to jnp.argmin).
// ---------------------------------------------------------------------------
__global__ __launch_bounds__(128)
void hungarian_kernel(int B) {
    __shared__ float sc[4][NN];
    const int w    = threadIdx.x >> 5;
    const int lane = threadIdx.x & 31;
    const int b    = blockIdx.x * 4 + w;
    if (b >= B) return;

    float* c = sc[w];
    const float* cg = g_cost + (size_t)b * NN;
    for (int t = lane; t < NN; t += 32) c[t] = cg[t];
    __syncwarp();

    const unsigned FULL = 0xffffffffu;
    float v  = 0.f;    // column potential
    float up = 0.f;    // u[p[lane]]
    int   p  = -1;     // row assigned to this column

    for (int i = 0; i < NSLOT; ++i) {
        if (lane == NSLOT) { p = i; up = 0.f; }
        float minv = HINF;
        int   way  = 0;
        bool  used = false;
        int   j0   = NSLOT;   // start at virtual column
        int   i0   = i;       // p[NSLOT] just set to i
        float u0   = 0.f;     // up[NSLOT] = 0

        for (int it = 0; it < NSLOT + 2; ++it) {
            if (lane == j0) used = true;
            float cur = (lane < NSLOT && !used) ? (c[i0 * NSLOT + lane] - u0 - v) : HINF;
            if (cur < minv) { minv = cur; way = j0; }
            float masked = (lane < NSLOT && !used) ? minv : HINF;

            unsigned bits = __float_as_uint(masked);
            unsigned key  = (bits & 0x80000000u) ? ~bits : (bits | 0x80000000u);
            unsigned mkey = __reduce_min_sync(FULL, key);
            float delta   = __uint_as_float((mkey & 0x80000000u) ? (mkey & 0x7fffffffu) : ~mkey);
            unsigned ball = __ballot_sync(FULL, key == mkey);
            int j1 = __ffs(ball) - 1;

            if (used)                { up += delta; v -= delta; }
            else if (lane < NSLOT)   { minv -= delta; }

            j0 = j1;
            i0 = __shfl_sync(FULL, p,  j0);   // prefetch for next iteration
            u0 = __shfl_sync(FULL, up, j0);   // (up already includes delta)
            if (i0 < 0) break;                // reached a free column
        }

        // augment back along the alternating path to the virtual column
        int j = j0;
        while (j != NSLOT) {
            int   jp  = __shfl_sync(FULL, way, j);
            int   pn_ = __shfl_sync(FULL, p,  jp);
            float un_ = __shfl_sync(FULL, up, jp);
            if (lane == j) { p = pn_; up = un_; }
            j = jp;
        }
    }
    // p = row matched to column `lane`  ->  col_ind[p] = lane
    if (lane < NSLOT) g_col[b * NSLOT + p] = lane;
}

// ---------------------------------------------------------------------------
// Kernel 3: gather.  out[b,r,:] = slots[b, col[b,r], :]  (float4 streaming)
// grid = B*6 blocks x 256 threads: exactly one float4 per thread -> full-chip
// MLP, unlike fusing it into the occupancy-starved hungarian kernel.
// ---------------------------------------------------------------------------
__global__ __launch_bounds__(256)
void gather_kernel(const float* __restrict__ slots, float* __restrict__ out) {
    const int bx = blockIdx.x;
    const int b  = bx / 6;
    const int within = (bx % 6) * 256 + threadIdx.x;   // 0..1535 (float4 idx in batch)
    const int r  = within >> 6;
    const int d4 = within & 63;
    const int src = g_col[b * NSLOT + r];
    const float4* sp = (const float4*)(slots + (size_t)b * (NSLOT * DDIM));
    float4 val = sp[src * 64 + d4];
    ((float4*)(out + (size_t)b * (NSLOT * DDIM)))[r * 64 + d4] = val;
}

// ---------------------------------------------------------------------------
extern "C" void kernel_launch(void* const* d_in, const int* in_sizes, int n_in,
                              void* d_out, int out_size) {
    const float* slots = (const float*)d_in[0];
    const float* prev  = (const float*)d_in[1];
    float* out = (float*)d_out;
    const int B = in_sizes[0] / (NSLOT * DDIM);   // 2048

    cudaFuncSetAttribute(cost_kernel, cudaFuncAttributeMaxDynamicSharedMemorySize, SMEM_BYTES);

    cost_kernel<<<B, 256, SMEM_BYTES>>>(slots, prev);
    hungarian_kernel<<<(B + 3) / 4, 128>>>(B);
    gather_kernel<<<B * 6, 256>>>(slots, out);
}

// round 14
// speedup vs baseline: 1.0261x; 1.0261x over previous
#include <cuda_runtime.h>
#include <cstdint>

// ---------------------------------------------------------------------------
// HungarianPredictor: B=2048, N=24, D=256
//   cost[b,i,j] = 1 - <normalize(prev[b,i]), normalize(slots[b,j])>
//   col = hungarian(cost)  (Jonker-Volgenant / e-maxx formulation)
//   out[b,i,:] = slots[b, col[b,i], :]
// ---------------------------------------------------------------------------

#define NSLOT   24
#define DDIM    256
#define ROWPAD  260                    // 1040 B row stride: 16B aligned, 8-lane-phase conflict-free
#define NN      (NSLOT * NSLOT)        // 576
#define MAXB    2048
#define HINF    1e9f

static const int SMEM_BYTES = 48 * ROWPAD * 4;   // 49,920 B (prev rows 0..23, cur rows 24..47)

__device__ float g_cost[MAXB * NN];
__device__ int   g_col [MAXB * NSLOT];

__device__ __forceinline__ unsigned long long fma2(unsigned long long a,
                                                   unsigned long long b,
                                                   unsigned long long c) {
    unsigned long long d;
    asm("fma.rn.f32x2 %0, %1, %2, %3;" : "=l"(d) : "l"(a), "l"(b), "l"(c));
    return d;
}

__device__ __forceinline__ float hsum2(unsigned long long v) {
    float lo = __uint_as_float((unsigned)(v & 0xffffffffu));
    float hi = __uint_as_float((unsigned)(v >> 32));
    return lo + hi;
}

// ---------------------------------------------------------------------------
// Kernel 1: persistent cost kernel, register double-buffered.
//   grid = 296 blocks x 256 threads; block walks batches b, b+296, ...
//   Per batch: store staged regs -> smem (+fused norms from regs) -> sync ->
//   ISSUE next batch's 12 LDG.128 (latency hides under the dot) ->
//   dot (warps 0-3: 6 prev rows broadcast + col LDS, lane j = col j) -> sync.
// ---------------------------------------------------------------------------
__global__ __launch_bounds__(256)
void cost_kernel(const float* __restrict__ slots, const float* __restrict__ prev,
                 int B, int G) {
    extern __shared__ float s[];
    __shared__ float s_inv[48];
    const int tid  = threadIdx.x;
    const int w    = tid >> 5;
    const int lane = tid & 31;

    // warp w stages 6 rows: w<4 -> prev rows 6w..6w+5, w>=4 -> cur rows
    const int    srow = (w < 4) ? 6 * w : NSLOT + 6 * (w - 4);
    const float* tsrc = (w < 4) ? prev : slots;
    const int    rofs = (w < 4) ? (6 * w) * DDIM : (6 * (w - 4)) * DDIM;

    float4 v0[6], v1[6];

    int b = blockIdx.x;
    // ---- prologue: load first batch into registers ----
    {
        const float* base = tsrc + (size_t)b * (NSLOT * DDIM) + rofs;
        #pragma unroll
        for (int rr = 0; rr < 6; ++rr) {
            const float4* rp = (const float4*)(base + rr * DDIM);
            v0[rr] = rp[lane];
            v1[rr] = rp[lane + 32];
        }
    }

    for (; b < B; b += G) {
        // ---- store regs -> smem + fused sum-of-squares (from regs) ----
        #pragma unroll
        for (int rr = 0; rr < 6; ++rr) {
            *(float4*)&s[(srow + rr) * ROWPAD + lane * 4]        = v0[rr];
            *(float4*)&s[(srow + rr) * ROWPAD + (lane + 32) * 4] = v1[rr];
            float ss = v0[rr].x * v0[rr].x;
            ss = fmaf(v0[rr].y, v0[rr].y, ss);
            ss = fmaf(v0[rr].z, v0[rr].z, ss);
            ss = fmaf(v0[rr].w, v0[rr].w, ss);
            ss = fmaf(v1[rr].x, v1[rr].x, ss);
            ss = fmaf(v1[rr].y, v1[rr].y, ss);
            ss = fmaf(v1[rr].z, v1[rr].z, ss);
            ss = fmaf(v1[rr].w, v1[rr].w, ss);
            #pragma unroll
            for (int o = 16; o; o >>= 1) ss += __shfl_xor_sync(0xffffffffu, ss, o);
            if (lane == 0) s_inv[srow + rr] = 1.f / fmaxf(sqrtf(ss), 1e-12f);
        }
        __syncthreads();

        // ---- prefetch next batch into registers (overlaps the dot below) ----
        const int nb = b + G;
        if (nb < B) {
            const float* base = tsrc + (size_t)nb * (NSLOT * DDIM) + rofs;
            #pragma unroll
            for (int rr = 0; rr < 6; ++rr) {
                const float4* rp = (const float4*)(base + rr * DDIM);
                v0[rr] = rp[lane];
                v1[rr] = rp[lane + 32];
            }
        }

        // ---- dot: warp w (<4) -> prev rows 6w..6w+5, lane j -> cur col j ----
        if (w < 4 && lane < NSLOT) {
            const int r0 = w * 6;
            const float* cj = &s[(NSLOT + lane) * ROWPAD];
            unsigned long long acc[6];
            #pragma unroll
            for (int rr = 0; rr < 6; ++rr) acc[rr] = 0ull;

            #pragma unroll 4
            for (int k4 = 0; k4 < 64; ++k4) {
                ulonglong2 c = *(const ulonglong2*)&cj[k4 * 4];      // conflict-free per 8-lane phase
                #pragma unroll
                for (int rr = 0; rr < 6; ++rr) {
                    ulonglong2 a = *(const ulonglong2*)&s[(r0 + rr) * ROWPAD + k4 * 4];  // broadcast (free)
                    acc[rr] = fma2(a.x, c.x, acc[rr]);
                    acc[rr] = fma2(a.y, c.y, acc[rr]);
                }
            }

            const float invj = s_inv[NSLOT + lane];
            float* cg = g_cost + (size_t)b * NN;
            #pragma unroll
            for (int rr = 0; rr < 6; ++rr)
                cg[(r0 + rr) * NSLOT + lane] = 1.f - hsum2(acc[rr]) * s_inv[r0 + rr] * invj;
        }
        __syncthreads();   // stage + s_inv reusable next iteration
    }
}

// ---------------------------------------------------------------------------
// Kernel 2: Hungarian (JV shortest augmenting path), one warp per batch.
// Lane j owns column j (j=24 is the virtual start column).  All duals in
// registers: v[j], minv[j], way[j], p[j], up[j]=u[p[j]].  (i0,u0) shuffled at
// the BOTTOM of the loop (merged with the break check) so the cost-row LDS
// issues at iteration start.  Argmin = order-preserving uint key + redux.min
// + ballot/ffs (first-index tie-break, identical to jnp.argmin).
// ---------------------------------------------------------------------------
__global__ __launch_bounds__(128)
void hungarian_kernel(int B) {
    __shared__ float sc[4][NN];
    const int w    = threadIdx.x >> 5;
    const int lane = threadIdx.x & 31;
    const int b    = blockIdx.x * 4 + w;
    if (b >= B) return;

    float* c = sc[w];
    const float* cg = g_cost + (size_t)b * NN;
    for (int t = lane; t < NN; t += 32) c[t] = cg[t];
    __syncwarp();

    const unsigned FULL = 0xffffffffu;
    float v  = 0.f;    // column potential
    float up = 0.f;    // u[p[lane]]
    int   p  = -1;     // row assigned to this column

    for (int i = 0; i < NSLOT; ++i) {
        if (lane == NSLOT) { p = i; up = 0.f; }
        float minv = HINF;
        int   way  = 0;
        bool  used = false;
        int   j0   = NSLOT;   // start at virtual column
        int   i0   = i;       // p[NSLOT] just set to i
        float u0   = 0.f;     // up[NSLOT] = 0

        for (int it = 0; it < NSLOT + 2; ++it) {
            if (lane == j0) used = true;
            float cur = (lane < NSLOT && !used) ? (c[i0 * NSLOT + lane] - u0 - v) : HINF;
            if (cur < minv) { minv = cur; way = j0; }
            float masked = (lane < NSLOT && !used) ? minv : HINF;

            unsigned bits = __float_as_uint(masked);
            unsigned key  = (bits & 0x80000000u) ? ~bits : (bits | 0x80000000u);
            unsigned mkey = __reduce_min_sync(FULL, key);
            float delta   = __uint_as_float((mkey & 0x80000000u) ? (mkey & 0x7fffffffu) : ~mkey);
            unsigned ball = __ballot_sync(FULL, key == mkey);
            int j1 = __ffs(ball) - 1;

            if (used)                { up += delta; v -= delta; }
            else if (lane < NSLOT)   { minv -= delta; }

            j0 = j1;
            i0 = __shfl_sync(FULL, p,  j0);   // prefetch for next iteration
            u0 = __shfl_sync(FULL, up, j0);   // (up already includes delta)
            if (i0 < 0) break;                // reached a free column
        }

        // augment back along the alternating path to the virtual column
        int j = j0;
        while (j != NSLOT) {
            int   jp  = __shfl_sync(FULL, way, j);
            int   pn_ = __shfl_sync(FULL, p,  jp);
            float un_ = __shfl_sync(FULL, up, jp);
            if (lane == j) { p = pn_; up = un_; }
            j = jp;
        }
    }
    // p = row matched to column `lane`  ->  col_ind[p] = lane
    if (lane < NSLOT) g_col[b * NSLOT + p] = lane;
}

// ---------------------------------------------------------------------------
// Kernel 3: gather.  out[b,r,:] = slots[b, col[b,r], :]  (float4 streaming)
// grid = B*6 blocks x 256 threads: exactly one float4 per thread -> full-chip
// MLP.
// ---------------------------------------------------------------------------
__global__ __launch_bounds__(256)
void gather_kernel(const float* __restrict__ slots, float* __restrict__ out) {
    const int bx = blockIdx.x;
    const int b  = bx / 6;
    const int within = (bx % 6) * 256 + threadIdx.x;   // 0..1535 (float4 idx in batch)
    const int r  = within >> 6;
    const int d4 = within & 63;
    const int src = g_col[b * NSLOT + r];
    const float4* sp = (const float4*)(slots + (size_t)b * (NSLOT * DDIM));
    float4 val = sp[src * 64 + d4];
    ((float4*)(out + (size_t)b * (NSLOT * DDIM)))[r * 64 + d4] = val;
}

// ---------------------------------------------------------------------------
extern "C" void kernel_launch(void* const* d_in, const int* in_sizes, int n_in,
                              void* d_out, int out_size) {
    const float* slots = (const float*)d_in[0];
    const float* prev  = (const float*)d_in[1];
    float* out = (float*)d_out;
    const int B = in_sizes[0] / (NSLOT * DDIM);   // 2048
    const int G = 296;                            // 2 blocks/SM x 148 SMs

    cudaFuncSetAttribute(cost_kernel, cudaFuncAttributeMaxDynamicSharedMemorySize, SMEM_BYTES);

    cost_kernel<<<G, 256, SMEM_BYTES>>>(slots, prev, B, G);
    hungarian_kernel<<<(B + 3) / 4, 128>>>(B);
    gather_kernel<<<B * 6, 256>>>(slots, out);
}

// round 15
// speedup vs baseline: 1.0421x; 1.0156x over previous
#include <cuda_runtime.h>
#include <cstdint>

// ---------------------------------------------------------------------------
// HungarianPredictor: B=2048, N=24, D=256  — fully fused single kernel.
//   Each block (256 thr) owns NB=8 consecutive batches:
//     Phase 1: cost matrices -> smem (no global scratch)
//     Phase 2: 8 concurrent warp-Hungarians (warp w -> batch w)
//     Phase 3: gather out[b,i,:] = slots[b, col[b,i], :]
//   3 blocks/SM: Hungarian latency chains overlap other blocks' DRAM phases.
// ---------------------------------------------------------------------------

#define NSLOT   24
#define DDIM    256
#define ROWPAD  260                    // 1040 B row stride: 16B aligned, 8-lane-phase conflict-free
#define NN      (NSLOT * NSLOT)        // 576
#define NB      8                      // batches per block (= warps per block)
#define HINF    1e9f

static const int SMEM_BYTES = 48 * ROWPAD * 4;   // 49,920 B dynamic staging

__device__ __forceinline__ unsigned long long fma2(unsigned long long a,
                                                   unsigned long long b,
                                                   unsigned long long c) {
    unsigned long long d;
    asm("fma.rn.f32x2 %0, %1, %2, %3;" : "=l"(d) : "l"(a), "l"(b), "l"(c));
    return d;
}

__device__ __forceinline__ float hsum2(unsigned long long v) {
    float lo = __uint_as_float((unsigned)(v & 0xffffffffu));
    float hi = __uint_as_float((unsigned)(v >> 32));
    return lo + hi;
}

__global__ __launch_bounds__(256, 3)
void fused_kernel(const float* __restrict__ slots, const float* __restrict__ prev,
                  float* __restrict__ out, int B) {
    extern __shared__ float s[];                 // staging: 48 rows x ROWPAD
    __shared__ float sc[NB][NN];                 // 8 cost matrices
    __shared__ int   scol[NB][NSLOT];            // col_ind per batch
    __shared__ float s_inv[48];
    const int tid  = threadIdx.x;
    const int w    = tid >> 5;
    const int lane = tid & 31;
    const int b0   = blockIdx.x * NB;
    const unsigned FULL = 0xffffffffu;

    // ======================= Phase 1: cost matrices =======================
    // warp w stages 6 rows: w<4 -> prev rows 6w..6w+5, w>=4 -> cur rows.
    const int    srow = (w < 4) ? 6 * w : NSLOT + 6 * (w - 4);
    const float* tsrc = (w < 4) ? prev : slots;
    const int    rofs = (w < 4) ? (6 * w) * DDIM : (6 * (w - 4)) * DDIM;

    for (int bb = 0; bb < NB; ++bb) {
        const int b = b0 + bb;
        if (b < B) {
            const float* base = tsrc + (size_t)b * (NSLOT * DDIM) + rofs;
            float4 v0[6], v1[6];
            #pragma unroll
            for (int rr = 0; rr < 6; ++rr) {       // 12 LDG.128 in flight
                const float4* rp = (const float4*)(base + rr * DDIM);
                v0[rr] = rp[lane];
                v1[rr] = rp[lane + 32];
            }
            #pragma unroll
            for (int rr = 0; rr < 6; ++rr) {
                *(float4*)&s[(srow + rr) * ROWPAD + lane * 4]        = v0[rr];
                *(float4*)&s[(srow + rr) * ROWPAD + (lane + 32) * 4] = v1[rr];
                float ss = v0[rr].x * v0[rr].x;
                ss = fmaf(v0[rr].y, v0[rr].y, ss);
                ss = fmaf(v0[rr].z, v0[rr].z, ss);
                ss = fmaf(v0[rr].w, v0[rr].w, ss);
                ss = fmaf(v1[rr].x, v1[rr].x, ss);
                ss = fmaf(v1[rr].y, v1[rr].y, ss);
                ss = fmaf(v1[rr].z, v1[rr].z, ss);
                ss = fmaf(v1[rr].w, v1[rr].w, ss);
                #pragma unroll
                for (int o = 16; o; o >>= 1) ss += __shfl_xor_sync(FULL, ss, o);
                if (lane == 0) s_inv[srow + rr] = 1.f / fmaxf(sqrtf(ss), 1e-12f);
            }
        }
        __syncthreads();

        // dot: warp w (<4) -> prev rows 6w..6w+5, lane j -> cur col j
        if (b < B && w < 4 && lane < NSLOT) {
            const int r0 = w * 6;
            const float* cj = &s[(NSLOT + lane) * ROWPAD];
            unsigned long long acc[6];
            #pragma unroll
            for (int rr = 0; rr < 6; ++rr) acc[rr] = 0ull;

            #pragma unroll 4
            for (int k4 = 0; k4 < 64; ++k4) {
                ulonglong2 c = *(const ulonglong2*)&cj[k4 * 4];  // conflict-free per 8-lane phase
                #pragma unroll
                for (int rr = 0; rr < 6; ++rr) {
                    ulonglong2 a = *(const ulonglong2*)&s[(r0 + rr) * ROWPAD + k4 * 4];  // broadcast
                    acc[rr] = fma2(a.x, c.x, acc[rr]);
                    acc[rr] = fma2(a.y, c.y, acc[rr]);
                }
            }

            const float invj = s_inv[NSLOT + lane];
            #pragma unroll
            for (int rr = 0; rr < 6; ++rr)
                sc[bb][(r0 + rr) * NSLOT + lane] = 1.f - hsum2(acc[rr]) * s_inv[r0 + rr] * invj;
        }
        __syncthreads();
    }

    // ================== Phase 2: 8 concurrent Hungarians ==================
    // Warp w solves batch b0+w on sc[w].  Lane j owns column j (j=24 = the
    // virtual start column).  Duals in registers: v, up=u[p], p, minv, way.
    // (i0,u0) shuffled at loop bottom merged with the break check.  Argmin =
    // order-preserving uint key + redux.min + ballot/ffs (first-index
    // tie-break, identical to jnp.argmin).  Augment: mark on-path lanes with
    // 1 shfl/step, then one parallel relink (2 shfls total).
    if (b0 + w < B) {
        const float* c = sc[w];
        float v  = 0.f;
        float up = 0.f;
        int   p  = -1;

        for (int i = 0; i < NSLOT; ++i) {
            if (lane == NSLOT) { p = i; up = 0.f; }
            float minv = HINF;
            int   way  = 0;
            bool  used = false;
            int   j0   = NSLOT;
            int   i0   = i;       // p[NSLOT] just set to i
            float u0   = 0.f;     // up[NSLOT] = 0

            for (int it = 0; it < NSLOT + 2; ++it) {
                if (lane == j0) used = true;
                float cur = (lane < NSLOT && !used) ? (c[i0 * NSLOT + lane] - u0 - v) : HINF;
                if (cur < minv) { minv = cur; way = j0; }
                float masked = (lane < NSLOT && !used) ? minv : HINF;

                unsigned bits = __float_as_uint(masked);
                unsigned key  = (bits & 0x80000000u) ? ~bits : (bits | 0x80000000u);
                unsigned mkey = __reduce_min_sync(FULL, key);
                float delta   = __uint_as_float((mkey & 0x80000000u) ? (mkey & 0x7fffffffu) : ~mkey);
                unsigned ball = __ballot_sync(FULL, key == mkey);
                int j1 = __ffs(ball) - 1;

                if (used)                { up += delta; v -= delta; }
                else if (lane < NSLOT)   { minv -= delta; }

                j0 = j1;
                i0 = __shfl_sync(FULL, p,  j0);   // prefetch next iteration
                u0 = __shfl_sync(FULL, up, j0);
                if (i0 < 0) break;                // reached a free column
            }

            // augment: walk path marking lanes (1 shfl/step), then relink
            bool onp = false;
            int  j   = j0;
            while (j != NSLOT) {
                if (lane == j) onp = true;
                j = __shfl_sync(FULL, way, j);
            }
            int   np  = __shfl_sync(FULL, p,  way);   // p[way[lane]] (old values)
            float nup = __shfl_sync(FULL, up, way);
            if (onp) { p = np; up = nup; }
        }
        // p = row matched to column `lane`  ->  col_ind[p] = lane
        if (lane < NSLOT) scol[w][p] = lane;
    }
    __syncthreads();

    // ========================= Phase 3: gather ===========================
    #pragma unroll
    for (int bb = 0; bb < NB; ++bb) {
        const int bg = b0 + bb;
        if (bg >= B) break;
        const float4* sp = (const float4*)(slots + (size_t)bg * (NSLOT * DDIM));
        float4*       op = (float4*)(out + (size_t)bg * (NSLOT * DDIM));
        #pragma unroll
        for (int idx = tid; idx < NSLOT * 64; idx += 256) {
            int r  = idx >> 6;
            int d4 = idx & 63;
            op[idx] = sp[scol[bb][r] * 64 + d4];
        }
    }
}

// ---------------------------------------------------------------------------
extern "C" void kernel_launch(void* const* d_in, const int* in_sizes, int n_in,
                              void* d_out, int out_size) {
    const float* slots = (const float*)d_in[0];
    const float* prev  = (const float*)d_in[1];
    float* out = (float*)d_out;
    const int B = in_sizes[0] / (NSLOT * DDIM);   // 2048

    cudaFuncSetAttribute(fused_kernel, cudaFuncAttributeMaxDynamicSharedMemorySize, SMEM_BYTES);

    const int grid = (B + NB - 1) / NB;           // 256 blocks
    fused_kernel<<<grid, 256, SMEM_BYTES>>>(slots, prev, out, B);
}